// round 6
// baseline (speedup 1.0000x reference)
#include <cuda_runtime.h>
#include <math.h>

#define BB 64
#define PP 256
#define NN 4096
#define SPLITK 64
#define KC (NN / SPLITK)   // 64
#define KCH 32             // k-chunk staged in smem

typedef unsigned long long ull;

// Interleaved (cos, sin) tables
__device__ __align__(16) float2 g_csphi[BB * NN];
__device__ __align__(16) float2 g_csxi[PP * NN];
__device__ float g_mpart[SPLITK * BB * PP];
__device__ float g_w[BB * PP];

// Packed fp32x2 FMA (Blackwell FFMA2) — two independent rn-FMAs per instruction
__device__ __forceinline__ ull ffma2(ull a, ull b, ull c) {
    ull d;
    asm("fma.rn.f32x2 %0, %1, %2, %3;" : "=l"(d) : "l"(a), "l"(b), "l"(c));
    return d;
}
__device__ __forceinline__ ull pack2(float x, float y) {
    ull r; asm("mov.b64 %0, {%1, %2};" : "=l"(r) : "f"(x), "f"(y)); return r;
}
__device__ __forceinline__ float2 unpack2(ull v) {
    float2 f; asm("mov.b64 {%0, %1}, %2;" : "=f"(f.x), "=f"(f.y) : "l"(v)); return f;
}

// ---------------------------------------------------------------------------
// Kernel 1: trig tables, interleaved (cos, sin)
// ---------------------------------------------------------------------------
__global__ __launch_bounds__(256) void trig_kernel(const float* __restrict__ phi,
                                                   const float* __restrict__ xi) {
    int i = blockIdx.x * 256 + threadIdx.x;
    if (i < BB * NN) {
        float s, c;
        sincosf(phi[i], &s, &c);
        g_csphi[i] = make_float2(c, s);
    } else if (i < (BB + PP) * NN) {
        int j = i - BB * NN;
        float s, c;
        sincosf(xi[j], &s, &c);
        g_csxi[j] = make_float2(c, s);
    }
}

// ---------------------------------------------------------------------------
// Kernel 2: m[b,p] = sum_k dot2(csphi[b,k], csxi[p,k]) via fma2.
// GEMM M=64(b), N=256(p), K=4096, split-K=64 (KC=64). grid=(4,64)=256 blocks.
// Block 256 thr (16x16), tile 64b x 64p, micro 4x4.
// B staged transposed [k][p] for contiguous conflict-free LDS.128.
// ---------------------------------------------------------------------------
__global__ __launch_bounds__(256) void mgemm_kernel() {
    __shared__ __align__(16) float4 Asm[64][17];   // [b][kpair] (c,s,c,s)
    __shared__ __align__(16) float2 Bsm[32][66];   // [k][p] transposed

    int p0 = blockIdx.x * 64;
    int k0 = blockIdx.y * KC;
    int tid = threadIdx.x;
    int tx = tid & 15;   // p group
    int ty = tid >> 4;   // b group

    ull acc[4][4] = {};

    const float4* A4 = (const float4*)g_csphi;
    const float4* B4 = (const float4*)g_csxi;

    for (int kk = 0; kk < KC; kk += KCH) {
        int kc4 = (k0 + kk) >> 1;  // float4 column base
#pragma unroll
        for (int i = tid; i < 64 * 16; i += 256) {
            int r = i >> 4, c = i & 15;
            Asm[r][c] = A4[r * (NN / 2) + kc4 + c];
            float4 v = B4[(p0 + r) * (NN / 2) + kc4 + c];
            Bsm[2 * c][r] = make_float2(v.x, v.y);
            Bsm[2 * c + 1][r] = make_float2(v.z, v.w);
        }
        __syncthreads();
#pragma unroll
        for (int kp = 0; kp < 16; kp++) {
            ulonglong2 av[4];
#pragma unroll
            for (int i = 0; i < 4; i++)
                av[i] = *(const ulonglong2*)&Asm[ty * 4 + i][kp];
            ulonglong2 b0a = *(const ulonglong2*)&Bsm[2 * kp][2 * tx];
            ulonglong2 b0b = *(const ulonglong2*)&Bsm[2 * kp][2 * tx + 32];
            ulonglong2 b1a = *(const ulonglong2*)&Bsm[2 * kp + 1][2 * tx];
            ulonglong2 b1b = *(const ulonglong2*)&Bsm[2 * kp + 1][2 * tx + 32];
#pragma unroll
            for (int i = 0; i < 4; i++) {
                acc[i][0] = ffma2(av[i].x, b0a.x, acc[i][0]);
                acc[i][1] = ffma2(av[i].x, b0a.y, acc[i][1]);
                acc[i][2] = ffma2(av[i].x, b0b.x, acc[i][2]);
                acc[i][3] = ffma2(av[i].x, b0b.y, acc[i][3]);
                acc[i][0] = ffma2(av[i].y, b1a.x, acc[i][0]);
                acc[i][1] = ffma2(av[i].y, b1a.y, acc[i][1]);
                acc[i][2] = ffma2(av[i].y, b1b.x, acc[i][2]);
                acc[i][3] = ffma2(av[i].y, b1b.y, acc[i][3]);
            }
        }
        __syncthreads();
    }

    float* outp = g_mpart + blockIdx.y * (BB * PP);
    int poff[4] = {2 * tx, 2 * tx + 1, 2 * tx + 32, 2 * tx + 33};
#pragma unroll
    for (int i = 0; i < 4; i++)
#pragma unroll
        for (int j = 0; j < 4; j++) {
            float2 f = unpack2(acc[i][j]);
            outp[(ty * 4 + i) * PP + p0 + poff[j]] = f.x + f.y;
        }
}

// ---------------------------------------------------------------------------
// Kernel 3: reduce split-K partials, softmax over p (per b). BETA=1.
// ---------------------------------------------------------------------------
__global__ __launch_bounds__(256) void softmax_kernel() {
    __shared__ float red[256];
    int b = blockIdx.x;
    int p = threadIdx.x;

    float s = 0.f;
#pragma unroll
    for (int sp = 0; sp < SPLITK; sp++)
        s += g_mpart[sp * BB * PP + b * PP + p];

    float val = s * (1.0f / (float)NN);

    red[p] = val;
    __syncthreads();
    for (int off = 128; off > 0; off >>= 1) {
        if (p < off) red[p] = fmaxf(red[p], red[p + off]);
        __syncthreads();
    }
    float mx = red[0];
    __syncthreads();

    float e = expf(val - mx);
    red[p] = e;
    __syncthreads();
    for (int off = 128; off > 0; off >>= 1) {
        if (p < off) red[p] += red[p + off];
        __syncthreads();
    }
    g_w[b * PP + p] = e / red[0];
}

// ---------------------------------------------------------------------------
// Kernel 4: coupling GEMM + epilogue, fma2 with (Wc,Ws) packed accumulators.
//   (Wc,Ws)[b,n] = sum_p w[b,p] * (cxi,sxi)[p,n]
//   out[b,n] = sphi*Wc - cphi*Ws + A*(sin(wt)*cphi - cos(wt)*sphi)
// Tile 64n x 16b, 128 threads (8 n-thr x 16 b-thr), micro 8n x 1b.
// grid = (NN/64, BB/16) = (64, 4) = 256 blocks.
// ---------------------------------------------------------------------------
__global__ __launch_bounds__(128) void coupling_kernel(const float* __restrict__ t,
                                                       float* __restrict__ out) {
    __shared__ __align__(16) float2 Csm[32][66];  // [p-chunk][n]
    __shared__ float Wsm[16][33];                 // [b][p-chunk]

    int n0 = blockIdx.x * 64;
    int b0 = blockIdx.y * 16;
    int tid = threadIdx.x;
    int nt = tid & 7;    // n thread
    int bt = tid >> 3;   // b thread

    ull acc[8] = {};
    const float4* X4 = (const float4*)g_csxi;

    for (int pk = 0; pk < PP; pk += 32) {
#pragma unroll
        for (int i = tid; i < 32 * 32; i += 128) {
            int r = i >> 5, c = i & 31;
            float4 v = X4[(pk + r) * (NN / 2) + (n0 >> 1) + c];
            Csm[r][2 * c] = make_float2(v.x, v.y);
            Csm[r][2 * c + 1] = make_float2(v.z, v.w);
        }
#pragma unroll
        for (int i = tid; i < 16 * 32; i += 128) {
            int r = i >> 5, c = i & 31;
            Wsm[r][c] = g_w[(b0 + r) * PP + pk + c];
        }
        __syncthreads();
#pragma unroll
        for (int p = 0; p < 32; p++) {
            float w = Wsm[bt][p];
            ull w2 = pack2(w, w);
#pragma unroll
            for (int g = 0; g < 4; g++) {
                ulonglong2 bv = *(const ulonglong2*)&Csm[p][2 * nt + 16 * g];
                acc[2 * g]     = ffma2(w2, bv.x, acc[2 * g]);
                acc[2 * g + 1] = ffma2(w2, bv.y, acc[2 * g + 1]);
            }
        }
        __syncthreads();
    }

    // Epilogue
    float tv = t[0];
    double sd, cd;
    sincos((double)(1256.6370614359172f * tv), &sd, &cd);
    float st = (float)sd, ct = (float)cd;

    int b = b0 + bt;
#pragma unroll
    for (int g = 0; g < 4; g++) {
        int n = n0 + 2 * nt + 16 * g;
        float2 w0 = unpack2(acc[2 * g]);      // (Wc, Ws) at n
        float2 w1 = unpack2(acc[2 * g + 1]);  // (Wc, Ws) at n+1
        float2 cs0 = g_csphi[b * NN + n];     // (cos phi, sin phi)
        float2 cs1 = g_csphi[b * NN + n + 1];
        float2 o;
        o.x = cs0.y * w0.x - cs0.x * w0.y + 0.08f * (st * cs0.x - ct * cs0.y);
        o.y = cs1.y * w1.x - cs1.x * w1.y + 0.08f * (st * cs1.x - ct * cs1.y);
        *(float2*)&out[b * NN + n] = o;
    }
}

// ---------------------------------------------------------------------------
extern "C" void kernel_launch(void* const* d_in, const int* in_sizes, int n_in,
                              void* d_out, int out_size) {
    const float* t = nullptr;
    const float* phi = nullptr;
    const float* xi = nullptr;
    for (int i = 0; i < n_in; i++) {
        if (in_sizes[i] == 1) t = (const float*)d_in[i];
        else if (in_sizes[i] == BB * NN) phi = (const float*)d_in[i];
        else if (in_sizes[i] == PP * NN) xi = (const float*)d_in[i];
    }
    float* out = (float*)d_out;

    trig_kernel<<<((BB + PP) * NN + 255) / 256, 256>>>(phi, xi);
    mgemm_kernel<<<dim3(PP / 64, SPLITK), 256>>>();
    softmax_kernel<<<BB, 256>>>();
    coupling_kernel<<<dim3(NN / 64, BB / 16), 128>>>(t, out);
}